// round 10
// baseline (speedup 1.0000x reference)
#include <cuda_runtime.h>

// Problem constants (from reference setup_inputs)
#define NB 4            // batch
#define EE 16           // embedding dims
#define HW 320000       // 400*800 pixels per image
#define NV (HW / 4)     // float4 groups per plane = 80000
#define CC 20           // label count
#define CK 19           // kept clusters (label 0 = IGNORE)
#define STR 17          // padded stride for [label][e] shared means
#define EB 4            // dim chunks of 4
#define P1_BPP 25       // pass1 blocks per (chunk, batch) plane
#define P1_T 128        // pass1 threads
#define P1_G 25         // groups per thread: 25*128*25 = 80000 = NV exactly
#define P2_BPB 185      // pass2 blocks per batch: 185*4 = 740 = 148 SM * 5

// Final accumulators (tiny; no replicas needed: only 25 REDs per address)
__device__ float4 g_red[CC * EB * NB];
__device__ float g_cnt[NB * CC];
__device__ float g_means[NB * CC * EE];
__device__ float g_var[NB * CC];
__device__ float g_distreg[NB];

__device__ __forceinline__ void red4(float4* p, float4 v) {
    asm volatile("red.global.add.v4.f32 [%0], {%1,%2,%3,%4};"
                 :: "l"(p), "f"(v.x), "f"(v.y), "f"(v.z), "f"(v.w) : "memory");
}

// ---------------------------------------------------------------------------
// Zero the accumulators (graph replays accumulate via RED -> must re-zero)
// ---------------------------------------------------------------------------
__global__ void k_zero() {
    int i = threadIdx.x;
    const float4 z4 = make_float4(0.f, 0.f, 0.f, 0.f);
    for (int j = i; j < CC * EB * NB; j += blockDim.x) g_red[j] = z4;
    for (int j = i; j < NB * CC; j += blockDim.x) { g_cnt[j] = 0.f; g_var[j] = 0.f; }
    if (i < NB) g_distreg[i] = 0.f;
}

// ---------------------------------------------------------------------------
// Pass 1: per-thread privatized segment sums. Block = (25 per plane, eb, n);
// owns dims [eb*4, eb*4+4). Each thread has a private [CC]+pad float4 region
// in smem -> plain LDS/FADD/STS, zero atomics in the hot loop. Epilogue:
// tree-reduce across threads, then one red.v4 per label per block.
// ---------------------------------------------------------------------------
__device__ __forceinline__ void p1_group(const float4* __restrict__ e0,
                                         const float4* __restrict__ e1,
                                         const float4* __restrict__ e2,
                                         const float4* __restrict__ e3,
                                         const int4* __restrict__ tgtn,
                                         int v, float4* my, float* sc, bool cnt) {
    int4 L = tgtn[v];
    float4 a = e0[v], b = e1[v], c = e2[v], d = e3[v];
    if (cnt) {
        atomicAdd(&sc[L.x], 1.f);
        atomicAdd(&sc[L.y], 1.f);
        atomicAdd(&sc[L.z], 1.f);
        atomicAdd(&sc[L.w], 1.f);
    }
    float4 t;
    t = my[L.x]; t.x += a.x; t.y += b.x; t.z += c.x; t.w += d.x; my[L.x] = t;
    t = my[L.y]; t.x += a.y; t.y += b.y; t.z += c.y; t.w += d.y; my[L.y] = t;
    t = my[L.z]; t.x += a.z; t.y += b.z; t.z += c.z; t.w += d.z; my[L.z] = t;
    t = my[L.w]; t.x += a.w; t.y += b.w; t.z += c.w; t.w += d.w; my[L.w] = t;
}

__global__ void __launch_bounds__(P1_T) k_pass1(const float* __restrict__ emb,
                                                const int* __restrict__ tgt) {
    const int eb = blockIdx.y;
    const int n  = blockIdx.z;
    const int tid = threadIdx.x;
    const bool docnt = (eb == 0);

    __shared__ float4 sacc[P1_T * (CC + 1)];   // 43008 B, per-thread regions
    __shared__ float scnt[4][32];

    float4* my = &sacc[tid * (CC + 1)];
#pragma unroll
    for (int j = 0; j < CC + 1; j++) my[j] = make_float4(0.f, 0.f, 0.f, 0.f);
    if (tid < 4 * 32) (&scnt[0][0])[tid] = 0.f;
    __syncthreads();

    const float4* emb4 = reinterpret_cast<const float4*>(emb);
    const float4* e0 = emb4 + (size_t)(n * EE + eb * 4 + 0) * NV;
    const float4* e1 = emb4 + (size_t)(n * EE + eb * 4 + 1) * NV;
    const float4* e2 = emb4 + (size_t)(n * EE + eb * 4 + 2) * NV;
    const float4* e3 = emb4 + (size_t)(n * EE + eb * 4 + 3) * NV;
    const int4* tgtn = reinterpret_cast<const int4*>(tgt) + (size_t)n * NV;
    float* sc = scnt[tid >> 5];

    const int vbase = blockIdx.x * (P1_T * P1_G) + tid;
#pragma unroll 1
    for (int i = 0; i < P1_G / 2; i++) {       // pairs for 2x MLP
        int v0 = vbase + i * (2 * P1_T);
        p1_group(e0, e1, e2, e3, tgtn, v0, my, sc, docnt);
        p1_group(e0, e1, e2, e3, tgtn, v0 + P1_T, my, sc, docnt);
    }
    p1_group(e0, e1, e2, e3, tgtn, vbase + (P1_G - 1) * P1_T, my, sc, docnt);

    // tree-reduce thread regions 128 -> 1
    for (int s = P1_T / 2; s > 0; s >>= 1) {
        __syncthreads();
        if (tid < s) {
            const float4* other = &sacc[(tid + s) * (CC + 1)];
#pragma unroll
            for (int lab = 0; lab < CC; lab++) {
                float4 t = my[lab], o = other[lab];
                t.x += o.x; t.y += o.y; t.z += o.z; t.w += o.w;
                my[lab] = t;
            }
        }
    }
    __syncthreads();

    if (tid < CC)
        red4(&g_red[(tid * EB + eb) * NB + n], sacc[tid]);   // region 0 lab=tid? no:
    // NOTE: after the tree, totals live in thread 0's region = sacc[0..CC).
    // sacc[tid] for tid<CC indexes exactly those slots since region 0 starts at 0.

    if (docnt && tid < CC) {
        float t = scnt[0][tid] + scnt[1][tid] + scnt[2][tid] + scnt[3][tid];
        atomicAdd(&g_cnt[n * CC + tid], t);
    }
}

// ---------------------------------------------------------------------------
// Means + distance (push) term + regularizer. One block per batch.
// ---------------------------------------------------------------------------
__global__ void __launch_bounds__(256) k_means() {
    const int n = blockIdx.x;
    __shared__ float m[CC * STR];
    __shared__ float cnt[CC];
    __shared__ float acc[2];
    const int tid = threadIdx.x;

    if (tid < 2) acc[tid] = 0.f;
    if (tid < CC) cnt[tid] = g_cnt[n * CC + tid];
    __syncthreads();

    const float* redf = reinterpret_cast<const float*>(g_red);
    for (int j = tid; j < CC * EE; j += blockDim.x) {
        int lab = j / EE, e = j % EE;
        float sum = redf[((lab * EB + (e >> 2)) * NB + n) * 4 + (e & 3)];
        float mv = sum / cnt[lab];
        m[lab * STR + e] = mv;
        g_means[n * CC * EE + j] = mv;
    }
    __syncthreads();

    // push term over kept clusters (labels 1..19)
    float part = 0.f;
    for (int pr = tid; pr < CK * CK; pr += blockDim.x) {
        int i = pr / CK + 1, j2 = pr % CK + 1;
        if (i != j2) {
            float d2 = 0.f;
#pragma unroll
            for (int e = 0; e < EE; e++) {
                float df = m[i * STR + e] - m[j2 * STR + e];
                d2 += df * df;
            }
            float dm = (d2 > 0.f) ? sqrtf(d2) : 0.f;
            float h = fmaxf(3.0f - dm, 0.f);   // 2*DELTA_DIST = 3
            part += h * h;
        }
    }
    // regularizer: sum of ||mean_k||
    float reg = 0.f;
    for (int c = tid + 1; c < CC; c += blockDim.x) {
        float d2 = 0.f;
#pragma unroll
        for (int e = 0; e < EE; e++) {
            float mv = m[c * STR + e];
            d2 += mv * mv;
        }
        reg += (d2 > 0.f) ? sqrtf(d2) : 0.f;
    }
    atomicAdd(&acc[0], part);
    atomicAdd(&acc[1], reg);
    __syncthreads();
    if (tid == 0)
        g_distreg[n] = acc[0] / (float)(CK * (CK - 1)) + 0.001f * acc[1] / (float)CK;
}

// ---------------------------------------------------------------------------
// Pass 2: variance (pull) term. Grid-stride, 740 blocks = 5/SM single wave.
// Per-warp sv replicas cut smem atomic contention.
// ---------------------------------------------------------------------------
__global__ void __launch_bounds__(256) k_pass2(const float* __restrict__ emb,
                                               const int* __restrict__ tgt) {
    const int n = blockIdx.y;
    __shared__ float m[CC * STR];
    __shared__ float svw[8][CC + 1];
    const int tid = threadIdx.x;

    for (int j = tid; j < CC * EE; j += blockDim.x) {
        int lab = j / EE, e = j % EE;
        m[lab * STR + e] = g_means[n * CC * EE + j];
    }
    for (int j = tid; j < 8 * (CC + 1); j += blockDim.x) (&svw[0][0])[j] = 0.f;
    __syncthreads();
    float* sv = svw[tid >> 5];

    const float4* embn = reinterpret_cast<const float4*>(emb) + (size_t)n * EE * NV;
    const int4*   tgtn = reinterpret_cast<const int4*>(tgt) + (size_t)n * NV;

    for (int v = blockIdx.x * blockDim.x + tid; v < NV;
         v += gridDim.x * blockDim.x) {
        int4 L = tgtn[v];
        int bx = L.x * STR, by = L.y * STR, bz = L.z * STR, bw = L.w * STR;
        float d0 = 0.f, d1 = 0.f, d2 = 0.f, d3 = 0.f;
#pragma unroll
        for (int e = 0; e < EE; e++) {
            float4 x = embn[(size_t)e * NV + v];
            float t0 = x.x - m[bx + e]; d0 = fmaf(t0, t0, d0);
            float t1 = x.y - m[by + e]; d1 = fmaf(t1, t1, d1);
            float t2 = x.z - m[bz + e]; d2 = fmaf(t2, t2, d2);
            float t3 = x.w - m[bw + e]; d3 = fmaf(t3, t3, d3);
        }
        if (L.x != 0) { float d = sqrtf(d0); float h = fmaxf(d - 0.5f, 0.f); atomicAdd(&sv[L.x], h * h); }
        if (L.y != 0) { float d = sqrtf(d1); float h = fmaxf(d - 0.5f, 0.f); atomicAdd(&sv[L.y], h * h); }
        if (L.z != 0) { float d = sqrtf(d2); float h = fmaxf(d - 0.5f, 0.f); atomicAdd(&sv[L.z], h * h); }
        if (L.w != 0) { float d = sqrtf(d3); float h = fmaxf(d - 0.5f, 0.f); atomicAdd(&sv[L.w], h * h); }
    }
    __syncthreads();
    if (tid < CC) {
        float t = 0.f;
#pragma unroll
        for (int w = 0; w < 8; w++) t += svw[w][tid];
        atomicAdd(&g_var[n * CC + tid], t);
    }
}

// ---------------------------------------------------------------------------
// Finalize: combine variance, distance, reg terms; mean over batches.
// ---------------------------------------------------------------------------
__global__ void k_final(float* __restrict__ out) {
    __shared__ float s[NB];
    const int tid = threadIdx.x;
    if (tid < NB) s[tid] = 0.f;
    __syncthreads();
    if (tid < NB * CK) {
        int n = tid / CK, c = tid % CK + 1;
        atomicAdd(&s[n], g_var[n * CC + c] / g_cnt[n * CC + c]);
    }
    __syncthreads();
    if (tid == 0) {
        float tot = 0.f;
        for (int n = 0; n < NB; n++)
            tot += s[n] / (float)CK + g_distreg[n];
        out[0] = tot / (float)NB;
    }
}

// ---------------------------------------------------------------------------
extern "C" void kernel_launch(void* const* d_in, const int* in_sizes, int n_in,
                              void* d_out, int out_size) {
    const float* emb = (const float*)d_in[0];
    const int*   tgt = (const int*)d_in[1];
    float*       out = (float*)d_out;

    k_zero<<<1, 256>>>();
    k_pass1<<<dim3(P1_BPP, EB, NB), P1_T>>>(emb, tgt);
    k_means<<<NB, 256>>>();
    k_pass2<<<dim3(P2_BPB, NB), 256>>>(emb, tgt);
    k_final<<<1, 128>>>(out);
}

// round 11
// speedup vs baseline: 1.1162x; 1.1162x over previous
#include <cuda_runtime.h>

// Problem constants (from reference setup_inputs)
#define NB 4            // batch
#define EE 16           // embedding dims
#define HW 320000       // 400*800 pixels per image
#define NV (HW / 4)     // float4 groups per plane = 80000
#define NV2 (NV / 2)    // 40000
#define CC 20           // label count
#define CK 19           // kept clusters (label 0 = IGNORE)
#define STR 17          // padded stride for [label][e] shared means
#define EB 4            // dim chunks of 4
#define P1_BPP 125      // pass1 blocks per (chunk, batch) plane
#define P1_T 128        // pass1 threads
#define P1_G 5          // groups per thread: 125*128*5 = 80000 = NV exactly
#define P2_BPB 157      // pass2 blocks per batch: 157*256 = 40192 >= NV2

// Final accumulators (tiny; only 125 REDs per address)
__device__ float4 g_red[CC * EB * NB];
__device__ float g_cnt[NB * CC];
__device__ float g_means[NB * CC * EE];
__device__ float g_var[NB * CC];
__device__ float g_distreg[NB];

__device__ __forceinline__ void red4(float4* p, float4 v) {
    asm volatile("red.global.add.v4.f32 [%0], {%1,%2,%3,%4};"
                 :: "l"(p), "f"(v.x), "f"(v.y), "f"(v.z), "f"(v.w) : "memory");
}

// ---------------------------------------------------------------------------
// Zero the accumulators (graph replays accumulate via RED -> must re-zero)
// ---------------------------------------------------------------------------
__global__ void k_zero() {
    int i = threadIdx.x;
    const float4 z4 = make_float4(0.f, 0.f, 0.f, 0.f);
    for (int j = i; j < CC * EB * NB; j += blockDim.x) g_red[j] = z4;
    for (int j = i; j < NB * CC; j += blockDim.x) { g_cnt[j] = 0.f; g_var[j] = 0.f; }
    if (i < NB) g_distreg[i] = 0.f;
}

// ---------------------------------------------------------------------------
// Pass 1: per-thread privatized segment sums, high-occupancy version.
// Block = (125 per plane, eb, n); owns dims [eb*4, eb*4+4). Each thread has a
// private [CC]+pad float4 region in smem (plain LDS/FADD/STS, no atomics).
// Two groups' gmem loads are issued together before their RMW chains.
// Epilogue: 3 tree rounds (128->16 regions), then 20 threads gather.
// ---------------------------------------------------------------------------
__device__ __forceinline__ void p1_accum(float4* my, int4 L,
                                         float4 a, float4 b, float4 c, float4 d) {
    float4 t;
    t = my[L.x]; t.x += a.x; t.y += b.x; t.z += c.x; t.w += d.x; my[L.x] = t;
    t = my[L.y]; t.x += a.y; t.y += b.y; t.z += c.y; t.w += d.y; my[L.y] = t;
    t = my[L.z]; t.x += a.z; t.y += b.z; t.z += c.z; t.w += d.z; my[L.z] = t;
    t = my[L.w]; t.x += a.w; t.y += b.w; t.z += c.w; t.w += d.w; my[L.w] = t;
}

__global__ void __launch_bounds__(P1_T) k_pass1(const float* __restrict__ emb,
                                                const int* __restrict__ tgt) {
    const int eb = blockIdx.y;
    const int n  = blockIdx.z;
    const int tid = threadIdx.x;
    const bool docnt = (eb == 0);

    __shared__ float4 sacc[P1_T * (CC + 1)];   // 43008 B, per-thread regions
    __shared__ float scnt[4][32];

    float4* my = &sacc[tid * (CC + 1)];
#pragma unroll
    for (int j = 0; j < CC + 1; j++) my[j] = make_float4(0.f, 0.f, 0.f, 0.f);
    if (tid < 4 * 32) (&scnt[0][0])[tid] = 0.f;
    __syncthreads();

    const float4* emb4 = reinterpret_cast<const float4*>(emb);
    const float4* e0 = emb4 + (size_t)(n * EE + eb * 4 + 0) * NV;
    const float4* e1 = emb4 + (size_t)(n * EE + eb * 4 + 1) * NV;
    const float4* e2 = emb4 + (size_t)(n * EE + eb * 4 + 2) * NV;
    const float4* e3 = emb4 + (size_t)(n * EE + eb * 4 + 3) * NV;
    const int4* tgtn = reinterpret_cast<const int4*>(tgt) + (size_t)n * NV;
    float* sc = scnt[tid >> 5];

    const int vbase = blockIdx.x * (P1_T * P1_G) + tid;

    // two interleaved pairs + one tail group
#pragma unroll 1
    for (int i = 0; i < P1_G / 2; i++) {
        const int v0 = vbase + (2 * i) * P1_T;
        const int v1 = v0 + P1_T;
        int4 L0 = tgtn[v0], L1 = tgtn[v1];
        float4 a0 = e0[v0], b0 = e1[v0], c0 = e2[v0], d0 = e3[v0];
        float4 a1 = e0[v1], b1 = e1[v1], c1 = e2[v1], d1 = e3[v1];
        if (docnt) {
            atomicAdd(&sc[L0.x], 1.f); atomicAdd(&sc[L0.y], 1.f);
            atomicAdd(&sc[L0.z], 1.f); atomicAdd(&sc[L0.w], 1.f);
            atomicAdd(&sc[L1.x], 1.f); atomicAdd(&sc[L1.y], 1.f);
            atomicAdd(&sc[L1.z], 1.f); atomicAdd(&sc[L1.w], 1.f);
        }
        p1_accum(my, L0, a0, b0, c0, d0);
        p1_accum(my, L1, a1, b1, c1, d1);
    }
    {
        const int v0 = vbase + (P1_G - 1) * P1_T;
        int4 L0 = tgtn[v0];
        float4 a0 = e0[v0], b0 = e1[v0], c0 = e2[v0], d0 = e3[v0];
        if (docnt) {
            atomicAdd(&sc[L0.x], 1.f); atomicAdd(&sc[L0.y], 1.f);
            atomicAdd(&sc[L0.z], 1.f); atomicAdd(&sc[L0.w], 1.f);
        }
        p1_accum(my, L0, a0, b0, c0, d0);
    }

    // tree-reduce 128 -> 16 regions
#pragma unroll
    for (int s = P1_T / 2; s >= 16; s >>= 1) {
        __syncthreads();
        if (tid < s) {
            const float4* other = &sacc[(tid + s) * (CC + 1)];
#pragma unroll
            for (int lab = 0; lab < CC; lab++) {
                float4 t = my[lab], o = other[lab];
                t.x += o.x; t.y += o.y; t.z += o.z; t.w += o.w;
                my[lab] = t;
            }
        }
    }
    __syncthreads();

    if (tid < CC) {
        float4 t = make_float4(0.f, 0.f, 0.f, 0.f);
#pragma unroll
        for (int r = 0; r < 16; r++) {
            float4 o = sacc[r * (CC + 1) + tid];
            t.x += o.x; t.y += o.y; t.z += o.z; t.w += o.w;
        }
        red4(&g_red[(tid * EB + eb) * NB + n], t);
    }

    if (docnt && tid < CC) {
        float t = scnt[0][tid] + scnt[1][tid] + scnt[2][tid] + scnt[3][tid];
        atomicAdd(&g_cnt[n * CC + tid], t);
    }
}

// ---------------------------------------------------------------------------
// Means + distance (push) term + regularizer. One block per batch.
// ---------------------------------------------------------------------------
__global__ void __launch_bounds__(256) k_means() {
    const int n = blockIdx.x;
    __shared__ float m[CC * STR];
    __shared__ float cnt[CC];
    __shared__ float acc[2];
    const int tid = threadIdx.x;

    if (tid < 2) acc[tid] = 0.f;
    if (tid < CC) cnt[tid] = g_cnt[n * CC + tid];
    __syncthreads();

    const float* redf = reinterpret_cast<const float*>(g_red);
    for (int j = tid; j < CC * EE; j += blockDim.x) {
        int lab = j / EE, e = j % EE;
        float sum = redf[((lab * EB + (e >> 2)) * NB + n) * 4 + (e & 3)];
        float mv = sum / cnt[lab];
        m[lab * STR + e] = mv;
        g_means[n * CC * EE + j] = mv;
    }
    __syncthreads();

    // push term over kept clusters (labels 1..19)
    float part = 0.f;
    for (int pr = tid; pr < CK * CK; pr += blockDim.x) {
        int i = pr / CK + 1, j2 = pr % CK + 1;
        if (i != j2) {
            float d2 = 0.f;
#pragma unroll
            for (int e = 0; e < EE; e++) {
                float df = m[i * STR + e] - m[j2 * STR + e];
                d2 += df * df;
            }
            float dm = (d2 > 0.f) ? sqrtf(d2) : 0.f;
            float h = fmaxf(3.0f - dm, 0.f);   // 2*DELTA_DIST = 3
            part += h * h;
        }
    }
    // regularizer: sum of ||mean_k||
    float reg = 0.f;
    for (int c = tid + 1; c < CC; c += blockDim.x) {
        float d2 = 0.f;
#pragma unroll
        for (int e = 0; e < EE; e++) {
            float mv = m[c * STR + e];
            d2 += mv * mv;
        }
        reg += (d2 > 0.f) ? sqrtf(d2) : 0.f;
    }
    atomicAdd(&acc[0], part);
    atomicAdd(&acc[1], reg);
    __syncthreads();
    if (tid == 0)
        g_distreg[n] = acc[0] / (float)(CK * (CK - 1)) + 0.001f * acc[1] / (float)CK;
}

// ---------------------------------------------------------------------------
// Pass 2: variance (pull) term. Each thread handles 2 float4 groups with
// fully interleaved loads (double MLP). Per-warp sv replicas for atomics.
// ---------------------------------------------------------------------------
__global__ void __launch_bounds__(256) k_pass2(const float* __restrict__ emb,
                                               const int* __restrict__ tgt) {
    const int n = blockIdx.y;
    __shared__ float m[CC * STR];
    __shared__ float svw[8][CC + 1];
    const int tid = threadIdx.x;

    for (int j = tid; j < CC * EE; j += blockDim.x) {
        int lab = j / EE, e = j % EE;
        m[lab * STR + e] = g_means[n * CC * EE + j];
    }
    for (int j = tid; j < 8 * (CC + 1); j += blockDim.x) (&svw[0][0])[j] = 0.f;
    __syncthreads();
    float* sv = svw[tid >> 5];

    const int idx = blockIdx.x * blockDim.x + tid;
    if (idx < NV2) {
        const float4* embn = reinterpret_cast<const float4*>(emb) + (size_t)n * EE * NV;
        const int4*   tgtn = reinterpret_cast<const int4*>(tgt) + (size_t)n * NV;
        const int v0 = idx, v1 = idx + NV2;

        int4 La = tgtn[v0], Lb = tgtn[v1];
        int ax = La.x * STR, ay = La.y * STR, az = La.z * STR, aw = La.w * STR;
        int bx = Lb.x * STR, by = Lb.y * STR, bz = Lb.z * STR, bw = Lb.w * STR;
        float a0 = 0.f, a1 = 0.f, a2 = 0.f, a3 = 0.f;
        float b0 = 0.f, b1 = 0.f, b2 = 0.f, b3 = 0.f;
#pragma unroll
        for (int e = 0; e < EE; e++) {
            float4 xa = embn[(size_t)e * NV + v0];
            float4 xb = embn[(size_t)e * NV + v1];
            float t;
            t = xa.x - m[ax + e]; a0 = fmaf(t, t, a0);
            t = xa.y - m[ay + e]; a1 = fmaf(t, t, a1);
            t = xa.z - m[az + e]; a2 = fmaf(t, t, a2);
            t = xa.w - m[aw + e]; a3 = fmaf(t, t, a3);
            t = xb.x - m[bx + e]; b0 = fmaf(t, t, b0);
            t = xb.y - m[by + e]; b1 = fmaf(t, t, b1);
            t = xb.z - m[bz + e]; b2 = fmaf(t, t, b2);
            t = xb.w - m[bw + e]; b3 = fmaf(t, t, b3);
        }
        if (La.x != 0) { float d = sqrtf(a0); float h = fmaxf(d - 0.5f, 0.f); atomicAdd(&sv[La.x], h * h); }
        if (La.y != 0) { float d = sqrtf(a1); float h = fmaxf(d - 0.5f, 0.f); atomicAdd(&sv[La.y], h * h); }
        if (La.z != 0) { float d = sqrtf(a2); float h = fmaxf(d - 0.5f, 0.f); atomicAdd(&sv[La.z], h * h); }
        if (La.w != 0) { float d = sqrtf(a3); float h = fmaxf(d - 0.5f, 0.f); atomicAdd(&sv[La.w], h * h); }
        if (Lb.x != 0) { float d = sqrtf(b0); float h = fmaxf(d - 0.5f, 0.f); atomicAdd(&sv[Lb.x], h * h); }
        if (Lb.y != 0) { float d = sqrtf(b1); float h = fmaxf(d - 0.5f, 0.f); atomicAdd(&sv[Lb.y], h * h); }
        if (Lb.z != 0) { float d = sqrtf(b2); float h = fmaxf(d - 0.5f, 0.f); atomicAdd(&sv[Lb.z], h * h); }
        if (Lb.w != 0) { float d = sqrtf(b3); float h = fmaxf(d - 0.5f, 0.f); atomicAdd(&sv[Lb.w], h * h); }
    }
    __syncthreads();
    if (tid < CC) {
        float t = 0.f;
#pragma unroll
        for (int w = 0; w < 8; w++) t += svw[w][tid];
        atomicAdd(&g_var[n * CC + tid], t);
    }
}

// ---------------------------------------------------------------------------
// Finalize: combine variance, distance, reg terms; mean over batches.
// ---------------------------------------------------------------------------
__global__ void k_final(float* __restrict__ out) {
    __shared__ float s[NB];
    const int tid = threadIdx.x;
    if (tid < NB) s[tid] = 0.f;
    __syncthreads();
    if (tid < NB * CK) {
        int n = tid / CK, c = tid % CK + 1;
        atomicAdd(&s[n], g_var[n * CC + c] / g_cnt[n * CC + c]);
    }
    __syncthreads();
    if (tid == 0) {
        float tot = 0.f;
        for (int n = 0; n < NB; n++)
            tot += s[n] / (float)CK + g_distreg[n];
        out[0] = tot / (float)NB;
    }
}

// ---------------------------------------------------------------------------
extern "C" void kernel_launch(void* const* d_in, const int* in_sizes, int n_in,
                              void* d_out, int out_size) {
    const float* emb = (const float*)d_in[0];
    const int*   tgt = (const int*)d_in[1];
    float*       out = (float*)d_out;

    k_zero<<<1, 256>>>();
    k_pass1<<<dim3(P1_BPP, EB, NB), P1_T>>>(emb, tgt);
    k_means<<<NB, 256>>>();
    k_pass2<<<dim3(P2_BPB, NB), 256>>>(emb, tgt);
    k_final<<<1, 128>>>(out);
}

// round 13
// speedup vs baseline: 1.1272x; 1.0099x over previous
#include <cuda_runtime.h>

// Problem constants (from reference setup_inputs)
#define NB 4            // batch
#define EE 16           // embedding dims
#define HW 320000       // 400*800 pixels per image
#define NV (HW / 4)     // float4 groups per plane = 80000
#define CC 20           // label count
#define CK 19           // kept clusters (label 0 = IGNORE)
#define STR 17          // padded stride for [label][e] shared means
#define EB 4            // dim chunks of 4
#define P1_BPP 125      // pass1 blocks per (chunk, batch) plane
#define P1_T 128        // pass1 threads
#define P1_G 5          // groups per thread: 125*128*5 = 80000 = NV exactly
#define P2_BPB 370      // pass2 blocks per batch: 370*4 = 1480 = 148 SM * 10... (8/SM at 2048thr)

// Final accumulators (tiny; only 125 REDs per address)
__device__ float4 g_red[CC * EB * NB];
__device__ float g_cnt[NB * CC];
__device__ float g_means[NB * CC * EE];
__device__ float g_var[NB * CC];
__device__ float g_distreg[NB];

__device__ __forceinline__ void red4(float4* p, float4 v) {
    asm volatile("red.global.add.v4.f32 [%0], {%1,%2,%3,%4};"
                 :: "l"(p), "f"(v.x), "f"(v.y), "f"(v.z), "f"(v.w) : "memory");
}

// ---------------------------------------------------------------------------
// Pass 1: per-thread privatized segment sums. Block = (125 per plane, eb, n);
// owns dims [eb*4, eb*4+4). Each thread has a private [CC]+pad float4 region
// in smem (plain LDS/FADD/STS, no atomics). Two groups' gmem loads issued
// together before their RMW chains. Epilogue: tree 128->16, 20-thread gather.
// NOTE: accumulators are zeroed here at entry (self-cleaning graph: k_final
// re-zeroes the global accumulators at the end of every execution).
// ---------------------------------------------------------------------------
__device__ __forceinline__ void p1_accum(float4* my, int4 L,
                                         float4 a, float4 b, float4 c, float4 d) {
    float4 t;
    t = my[L.x]; t.x += a.x; t.y += b.x; t.z += c.x; t.w += d.x; my[L.x] = t;
    t = my[L.y]; t.x += a.y; t.y += b.y; t.z += c.y; t.w += d.y; my[L.y] = t;
    t = my[L.z]; t.x += a.z; t.y += b.z; t.z += c.z; t.w += d.z; my[L.z] = t;
    t = my[L.w]; t.x += a.w; t.y += b.w; t.z += c.w; t.w += d.w; my[L.w] = t;
}

__global__ void __launch_bounds__(P1_T) k_pass1(const float* __restrict__ emb,
                                                const int* __restrict__ tgt) {
    const int eb = blockIdx.y;
    const int n  = blockIdx.z;
    const int tid = threadIdx.x;
    const bool docnt = (eb == 0);

    __shared__ float4 sacc[P1_T * (CC + 1)];   // 43008 B, per-thread regions
    __shared__ float scnt[4][32];

    float4* my = &sacc[tid * (CC + 1)];
#pragma unroll
    for (int j = 0; j < CC + 1; j++) my[j] = make_float4(0.f, 0.f, 0.f, 0.f);
    if (tid < 4 * 32) (&scnt[0][0])[tid] = 0.f;
    __syncthreads();

    const float4* emb4 = reinterpret_cast<const float4*>(emb);
    const float4* e0 = emb4 + (size_t)(n * EE + eb * 4 + 0) * NV;
    const float4* e1 = emb4 + (size_t)(n * EE + eb * 4 + 1) * NV;
    const float4* e2 = emb4 + (size_t)(n * EE + eb * 4 + 2) * NV;
    const float4* e3 = emb4 + (size_t)(n * EE + eb * 4 + 3) * NV;
    const int4* tgtn = reinterpret_cast<const int4*>(tgt) + (size_t)n * NV;
    float* sc = scnt[tid >> 5];

    const int vbase = blockIdx.x * (P1_T * P1_G) + tid;

#pragma unroll 1
    for (int i = 0; i < P1_G / 2; i++) {
        const int v0 = vbase + (2 * i) * P1_T;
        const int v1 = v0 + P1_T;
        int4 L0 = tgtn[v0], L1 = tgtn[v1];
        float4 a0 = e0[v0], b0 = e1[v0], c0 = e2[v0], d0 = e3[v0];
        float4 a1 = e0[v1], b1 = e1[v1], c1 = e2[v1], d1 = e3[v1];
        if (docnt) {
            atomicAdd(&sc[L0.x], 1.f); atomicAdd(&sc[L0.y], 1.f);
            atomicAdd(&sc[L0.z], 1.f); atomicAdd(&sc[L0.w], 1.f);
            atomicAdd(&sc[L1.x], 1.f); atomicAdd(&sc[L1.y], 1.f);
            atomicAdd(&sc[L1.z], 1.f); atomicAdd(&sc[L1.w], 1.f);
        }
        p1_accum(my, L0, a0, b0, c0, d0);
        p1_accum(my, L1, a1, b1, c1, d1);
    }
    {
        const int v0 = vbase + (P1_G - 1) * P1_T;
        int4 L0 = tgtn[v0];
        float4 a0 = e0[v0], b0 = e1[v0], c0 = e2[v0], d0 = e3[v0];
        if (docnt) {
            atomicAdd(&sc[L0.x], 1.f); atomicAdd(&sc[L0.y], 1.f);
            atomicAdd(&sc[L0.z], 1.f); atomicAdd(&sc[L0.w], 1.f);
        }
        p1_accum(my, L0, a0, b0, c0, d0);
    }

    // tree-reduce 128 -> 16 regions
#pragma unroll
    for (int s = P1_T / 2; s >= 16; s >>= 1) {
        __syncthreads();
        if (tid < s) {
            const float4* other = &sacc[(tid + s) * (CC + 1)];
#pragma unroll
            for (int lab = 0; lab < CC; lab++) {
                float4 t = my[lab], o = other[lab];
                t.x += o.x; t.y += o.y; t.z += o.z; t.w += o.w;
                my[lab] = t;
            }
        }
    }
    __syncthreads();

    if (tid < CC) {
        float4 t = make_float4(0.f, 0.f, 0.f, 0.f);
#pragma unroll
        for (int r = 0; r < 16; r++) {
            float4 o = sacc[r * (CC + 1) + tid];
            t.x += o.x; t.y += o.y; t.z += o.z; t.w += o.w;
        }
        red4(&g_red[(tid * EB + eb) * NB + n], t);
    }

    if (docnt && tid < CC) {
        float t = scnt[0][tid] + scnt[1][tid] + scnt[2][tid] + scnt[3][tid];
        atomicAdd(&g_cnt[n * CC + tid], t);
    }
}

// ---------------------------------------------------------------------------
// Means + distance (push) term + regularizer. One block per batch.
// ---------------------------------------------------------------------------
__global__ void __launch_bounds__(256) k_means() {
    const int n = blockIdx.x;
    __shared__ float m[CC * STR];
    __shared__ float cnt[CC];
    __shared__ float acc[2];
    const int tid = threadIdx.x;

    if (tid < 2) acc[tid] = 0.f;
    if (tid < CC) cnt[tid] = g_cnt[n * CC + tid];
    __syncthreads();

    const float* redf = reinterpret_cast<const float*>(g_red);
    for (int j = tid; j < CC * EE; j += blockDim.x) {
        int lab = j / EE, e = j % EE;
        float sum = redf[((lab * EB + (e >> 2)) * NB + n) * 4 + (e & 3)];
        float mv = sum / cnt[lab];
        m[lab * STR + e] = mv;
        g_means[n * CC * EE + j] = mv;
    }
    __syncthreads();

    // push term over kept clusters (labels 1..19)
    float part = 0.f;
    for (int pr = tid; pr < CK * CK; pr += blockDim.x) {
        int i = pr / CK + 1, j2 = pr % CK + 1;
        if (i != j2) {
            float d2 = 0.f;
#pragma unroll
            for (int e = 0; e < EE; e++) {
                float df = m[i * STR + e] - m[j2 * STR + e];
                d2 += df * df;
            }
            float dm = (d2 > 0.f) ? sqrtf(d2) : 0.f;
            float h = fmaxf(3.0f - dm, 0.f);   // 2*DELTA_DIST = 3
            part += h * h;
        }
    }
    // regularizer: sum of ||mean_k||
    float reg = 0.f;
    for (int c = tid + 1; c < CC; c += blockDim.x) {
        float d2 = 0.f;
#pragma unroll
        for (int e = 0; e < EE; e++) {
            float mv = m[c * STR + e];
            d2 += mv * mv;
        }
        reg += (d2 > 0.f) ? sqrtf(d2) : 0.f;
    }
    atomicAdd(&acc[0], part);
    atomicAdd(&acc[1], reg);
    __syncthreads();
    if (tid == 0)
        g_distreg[n] = acc[0] / (float)(CK * (CK - 1)) + 0.001f * acc[1] / (float)CK;
}

// ---------------------------------------------------------------------------
// Pass 2: variance (pull) term. Single-group body (low regs), occupancy
// forced to 8 blocks/SM via launch bounds; 1480 blocks = single full wave.
// Per-warp sv replicas cut smem atomic contention.
// ---------------------------------------------------------------------------
__global__ void __launch_bounds__(256, 8) k_pass2(const float* __restrict__ emb,
                                                  const int* __restrict__ tgt) {
    const int n = blockIdx.y;
    __shared__ float m[CC * STR];
    __shared__ float svw[8][CC + 1];
    const int tid = threadIdx.x;

    for (int j = tid; j < CC * EE; j += blockDim.x) {
        int lab = j / EE, e = j % EE;
        m[lab * STR + e] = g_means[n * CC * EE + j];
    }
    for (int j = tid; j < 8 * (CC + 1); j += blockDim.x) (&svw[0][0])[j] = 0.f;
    __syncthreads();
    float* sv = svw[tid >> 5];

    const float4* embn = reinterpret_cast<const float4*>(emb) + (size_t)n * EE * NV;
    const int4*   tgtn = reinterpret_cast<const int4*>(tgt) + (size_t)n * NV;

    for (int v = blockIdx.x * blockDim.x + tid; v < NV;
         v += gridDim.x * blockDim.x) {
        int4 L = tgtn[v];
        int bx = L.x * STR, by = L.y * STR, bz = L.z * STR, bw = L.w * STR;
        float d0 = 0.f, d1 = 0.f, d2 = 0.f, d3 = 0.f;
#pragma unroll
        for (int e = 0; e < EE; e++) {
            float4 x = embn[(size_t)e * NV + v];
            float t0 = x.x - m[bx + e]; d0 = fmaf(t0, t0, d0);
            float t1 = x.y - m[by + e]; d1 = fmaf(t1, t1, d1);
            float t2 = x.z - m[bz + e]; d2 = fmaf(t2, t2, d2);
            float t3 = x.w - m[bw + e]; d3 = fmaf(t3, t3, d3);
        }
        if (L.x != 0) { float d = sqrtf(d0); float h = fmaxf(d - 0.5f, 0.f); atomicAdd(&sv[L.x], h * h); }
        if (L.y != 0) { float d = sqrtf(d1); float h = fmaxf(d - 0.5f, 0.f); atomicAdd(&sv[L.y], h * h); }
        if (L.z != 0) { float d = sqrtf(d2); float h = fmaxf(d - 0.5f, 0.f); atomicAdd(&sv[L.z], h * h); }
        if (L.w != 0) { float d = sqrtf(d3); float h = fmaxf(d - 0.5f, 0.f); atomicAdd(&sv[L.w], h * h); }
    }
    __syncthreads();
    if (tid < CC) {
        float t = 0.f;
#pragma unroll
        for (int w = 0; w < 8; w++) t += svw[w][tid];
        atomicAdd(&g_var[n * CC + tid], t);
    }
}

// ---------------------------------------------------------------------------
// Finalize: combine terms, write output, then re-zero all accumulators so the
// next graph replay starts clean (replaces the k_zero kernel).
// ---------------------------------------------------------------------------
__global__ void k_final(float* __restrict__ out) {
    __shared__ float s[NB];
    const int tid = threadIdx.x;
    if (tid < NB) s[tid] = 0.f;
    __syncthreads();
    if (tid < NB * CK) {
        int n = tid / CK, c = tid % CK + 1;
        atomicAdd(&s[n], g_var[n * CC + c] / g_cnt[n * CC + c]);
    }
    __syncthreads();
    if (tid == 0) {
        float tot = 0.f;
        for (int n = 0; n < NB; n++)
            tot += s[n] / (float)CK + g_distreg[n];
        out[0] = tot / (float)NB;
    }
    // self-clean for the next execution
    const float4 z4 = make_float4(0.f, 0.f, 0.f, 0.f);
    for (int j = tid; j < CC * EB * NB; j += blockDim.x) g_red[j] = z4;
    for (int j = tid; j < NB * CC; j += blockDim.x) { g_cnt[j] = 0.f; g_var[j] = 0.f; }
    if (tid < NB) g_distreg[tid] = 0.f;
}

// ---------------------------------------------------------------------------
extern "C" void kernel_launch(void* const* d_in, const int* in_sizes, int n_in,
                              void* d_out, int out_size) {
    const float* emb = (const float*)d_in[0];
    const int*   tgt = (const int*)d_in[1];
    float*       out = (float*)d_out;

    k_pass1<<<dim3(P1_BPP, EB, NB), P1_T>>>(emb, tgt);
    k_means<<<NB, 256>>>();
    k_pass2<<<dim3(P2_BPB, NB), 256>>>(emb, tgt);
    k_final<<<1, 128>>>(out);
}